// round 2
// baseline (speedup 1.0000x reference)
#include <cuda_runtime.h>
#include <cuda_fp8.h>
#include <cuda_bf16.h>

#define S_N     32
#define NHEAD   32
#define HDIM    128
#define NKVH    8
#define GQ      4
#define BSZ     16
#define MBLK    128
#define NSPLIT  16
#define CHUNK   128
#define TILE    32
#define ROWF    132
#define ATTN_SCALE 0.08838834764831845f
#define NEG_BIG   -3.402823466e38f

// split-KV partial scratch (static device memory: allocation-free)
__device__ float g_po[S_N][NKVH][NSPLIT][GQ][HDIM];
__device__ float g_pm[S_N][NKVH][NSPLIT][GQ];
__device__ float g_pl[S_N][NKVH][NSPLIT][GQ];

// Exact emulation of reference dequant: bf16( f32(e4m3_satfinite_rn(c)) * scale )
__device__ __forceinline__ float4 dq4(float4 c, float s) {
    float2 a = make_float2(c.x, c.y);
    float2 b = make_float2(c.z, c.w);
    __nv_fp8x2_storage_t p0 = __nv_cvt_float2_to_fp8x2(a, __NV_SATFINITE, __NV_E4M3);
    __nv_fp8x2_storage_t p1 = __nv_cvt_float2_to_fp8x2(b, __NV_SATFINITE, __NV_E4M3);
    __half2_raw h0 = __nv_cvt_fp8x2_to_halfraw2(p0, __NV_E4M3);
    __half2_raw h1 = __nv_cvt_fp8x2_to_halfraw2(p1, __NV_E4M3);
    float2 f0 = __half22float2(*reinterpret_cast<__half2*>(&h0));
    float2 f1 = __half22float2(*reinterpret_cast<__half2*>(&h1));
    f0.x *= s; f0.y *= s; f1.x *= s; f1.y *= s;
    __nv_bfloat162 bb0 = __float22bfloat162_rn(f0);
    __nv_bfloat162 bb1 = __float22bfloat162_rn(f1);
    unsigned u0 = *reinterpret_cast<unsigned*>(&bb0);
    unsigned u1 = *reinterpret_cast<unsigned*>(&bb1);
    float4 r;
    r.x = __uint_as_float(u0 << 16);
    r.y = __uint_as_float(u0 & 0xFFFF0000u);
    r.z = __uint_as_float(u1 << 16);
    r.w = __uint_as_float(u1 & 0xFFFF0000u);
    return r;
}

__global__ void __launch_bounds__(128)
attn_main_kernel(const float* __restrict__ q, const float* __restrict__ knew,
                 const float* __restrict__ vnew, const float* __restrict__ kcache,
                 const float* __restrict__ vcache, const float* __restrict__ kscale_p,
                 const float* __restrict__ vscale_p, const int* __restrict__ btab,
                 const int* __restrict__ clen)
{
    const int split = blockIdx.x;
    const int h     = blockIdx.y;
    const int s     = blockIdx.z;
    const int ctx   = clen[s];
    const int c0    = split * CHUNK;
    if (c0 >= ctx) return;
    const int nvalid = min(CHUNK, ctx - c0);
    const int ntile  = (nvalid + TILE - 1) / TILE;

    __shared__ float kt[TILE][ROWF];   // dequantized K tile (padded: conflict-free LDS.128)
    __shared__ float vt[TILE][ROWF];   // dequantized V tile
    __shared__ float qs[GQ * HDIM];

    const int t = threadIdx.x;
    const int w = t >> 5;     // warp = query head within GQA group
    const int l = t & 31;     // lane

    // stage Q (512 floats, raw f32 as in reference)
    ((float4*)qs)[t] = ((const float4*)(q + (size_t)s * (NHEAD * HDIM)
                                          + (size_t)h * (GQ * HDIM)))[t];
    const float ks = kscale_p[h];
    const float vs = vscale_p[h];

    float  m    = NEG_BIG;
    float  lsum = 0.f;
    float4 o    = make_float4(0.f, 0.f, 0.f, 0.f);

    for (int tb = 0; tb < ntile; ++tb) {
        const int base = c0 + tb * TILE;

        // ---- stage + dequantize K/V tile: warp w loads rows (i*4 + w), full 512B rows coalesced
        #pragma unroll
        for (int i = 0; i < 8; ++i) {
            const int pl = i * 4 + w;          // tile-local position 0..31
            const int P  = base + pl;          // global position (< 2048 always: safe loads)
            const long long blk  = (long long)btab[s * MBLK + (P >> 4)];
            const long long roff = ((blk * BSZ + (P & 15)) * NKVH + h) * (long long)HDIM;
            float4 kv = ((const float4*)(kcache + roff))[l];
            float4 vv = ((const float4*)(vcache + roff))[l];
            if (P == ctx - 1) {  // new token: reference scatters fp8(k/scale) at this slot
                const float* kp = knew + (size_t)s * (NKVH * HDIM) + h * HDIM + l * 4;
                const float* vp = vnew + (size_t)s * (NKVH * HDIM) + h * HDIM + l * 4;
                kv.x = __fdiv_rn(kp[0], ks); kv.y = __fdiv_rn(kp[1], ks);
                kv.z = __fdiv_rn(kp[2], ks); kv.w = __fdiv_rn(kp[3], ks);
                vv.x = __fdiv_rn(vp[0], vs); vv.y = __fdiv_rn(vp[1], vs);
                vv.z = __fdiv_rn(vp[2], vs); vv.w = __fdiv_rn(vp[3], vs);
            }
            *(float4*)&kt[pl][l * 4] = dq4(kv, ks);
            *(float4*)&vt[pl][l * 4] = dq4(vv, vs);
        }
        __syncthreads();

        // ---- scores: warp w = head w, lane l = position l (no cross-lane reduction of dots)
        float4 acc = make_float4(0.f, 0.f, 0.f, 0.f);
        #pragma unroll
        for (int d4 = 0; d4 < 32; ++d4) {
            const float4 kv = *(const float4*)&kt[l][d4 * 4];
            const float4 qv = *(const float4*)&qs[w * HDIM + d4 * 4];
            acc.x += kv.x * qv.x; acc.y += kv.y * qv.y;
            acc.z += kv.z * qv.z; acc.w += kv.w * qv.w;
        }
        float sc = ((acc.x + acc.y) + (acc.z + acc.w)) * ATTN_SCALE;
        if (base + l >= ctx) sc = NEG_BIG;

        // online softmax (per warp)
        float tm = sc;
        #pragma unroll
        for (int off = 16; off > 0; off >>= 1)
            tm = fmaxf(tm, __shfl_xor_sync(0xFFFFFFFFu, tm, off));
        const float mnew  = fmaxf(m, tm);
        const float alpha = __expf(m - mnew);
        const float p     = __expf(sc - mnew);   // masked lanes underflow to 0
        float tsum = p;
        #pragma unroll
        for (int off = 16; off > 0; off >>= 1)
            tsum += __shfl_xor_sync(0xFFFFFFFFu, tsum, off);
        lsum = lsum * alpha + tsum;
        m = mnew;

        // ---- accumulate O: lane l owns dims 4l..4l+3; weights broadcast by shuffle
        o.x *= alpha; o.y *= alpha; o.z *= alpha; o.w *= alpha;
        #pragma unroll
        for (int pp = 0; pp < 32; ++pp) {
            const float  wgt = __shfl_sync(0xFFFFFFFFu, p, pp);
            const float4 vv  = *(const float4*)&vt[pp][l * 4];
            o.x += wgt * vv.x; o.y += wgt * vv.y;
            o.z += wgt * vv.z; o.w += wgt * vv.w;
        }
        __syncthreads();
    }

    *(float4*)&g_po[s][h][split][w][l * 4] = o;
    if (l == 0) { g_pm[s][h][split][w] = m; g_pl[s][h][split][w] = lsum; }
}

__global__ void __launch_bounds__(128)
attn_combine_kernel(const int* __restrict__ clen, float* __restrict__ out)
{
    const int h   = blockIdx.x;
    const int s   = blockIdx.y;
    const int ctx = clen[s];
    const int nsp = (ctx + CHUNK - 1) / CHUNK;
    const int t = threadIdx.x;
    const int g = t >> 5;
    const int l = t & 31;

    float M = NEG_BIG;
    for (int i = 0; i < nsp; ++i) M = fmaxf(M, g_pm[s][h][i][g]);
    float L = 0.f;
    float4 acc = make_float4(0.f, 0.f, 0.f, 0.f);
    for (int i = 0; i < nsp; ++i) {
        const float wi = __expf(g_pm[s][h][i][g] - M);
        L += g_pl[s][h][i][g] * wi;
        const float4 pv = *(const float4*)&g_po[s][h][i][g][l * 4];
        acc.x += wi * pv.x; acc.y += wi * pv.y;
        acc.z += wi * pv.z; acc.w += wi * pv.w;
    }
    const float inv = 1.f / L;
    float4 r = make_float4(acc.x * inv, acc.y * inv, acc.z * inv, acc.w * inv);
    *(float4*)(out + (size_t)s * (NHEAD * HDIM) + (size_t)(h * GQ + g) * HDIM + l * 4) = r;
}

extern "C" void kernel_launch(void* const* d_in, const int* in_sizes, int n_in,
                              void* d_out, int out_size) {
    (void)in_sizes; (void)n_in; (void)out_size;
    const float* q    = (const float*)d_in[0];
    const float* k    = (const float*)d_in[1];
    const float* v    = (const float*)d_in[2];
    const float* kc   = (const float*)d_in[3];
    const float* vc   = (const float*)d_in[4];
    const float* ksc  = (const float*)d_in[5];
    const float* vsc  = (const float*)d_in[6];
    // d_in[7] slot_mapping: unused (position ctx-1 substitution is equivalent)
    const int*   btab = (const int*)d_in[8];   // JAX x64 disabled -> int32
    const int*   clen = (const int*)d_in[9];

    dim3 g1(NSPLIT, NKVH, S_N);
    attn_main_kernel<<<g1, 128>>>(q, k, v, kc, vc, ksc, vsc, btab, clen);
    dim3 g2(NKVH, S_N);
    attn_combine_kernel<<<g2, 128>>>(clen, (float*)d_out);
}